// round 14
// baseline (speedup 1.0000x reference)
#include <cuda_runtime.h>
#include <cstdint>

#define T_STEPS 2048
#define HID 64
#define EPB 7
#define NTHR 512
#define Q (EPB * HID)            // 448 floats per h slot
#define SQ2 512                  // psh q-slot stride in float2 units (4*64 float4)

typedef unsigned long long u64;

// ---------- f32x2 packed math ----------
__device__ __forceinline__ u64 fma2(u64 a, u64 b, u64 c) {
    u64 d; asm("fma.rn.f32x2 %0, %1, %2, %3;" : "=l"(d) : "l"(a), "l"(b), "l"(c)); return d;
}
__device__ __forceinline__ u64 mul2(u64 a, u64 b) {
    u64 d; asm("mul.rn.f32x2 %0, %1, %2;" : "=l"(d) : "l"(a), "l"(b)); return d;
}
__device__ __forceinline__ u64 pack2(float lo, float hi) {
    u64 d; asm("mov.b64 %0, {%1, %2};" : "=l"(d) : "f"(lo), "f"(hi)); return d;
}
__device__ __forceinline__ float2 unpack2(u64 v) {
    float a, b; asm("mov.b64 {%0, %1}, %2;" : "=f"(a), "=f"(b) : "l"(v));
    return make_float2(a, b);
}

// ---------- fast activations: MUFU.TANH ----------
__device__ __forceinline__ float tanh_fast(float x) {
    float r; asm("tanh.approx.f32 %0, %1;" : "=f"(r) : "f"(x)); return r;
}
__device__ __forceinline__ float sig_fast(float x) {
    return fmaf(tanh_fast(0.5f * x), 0.5f, 0.5f);
}

extern __shared__ float smem_f[];
// SMEM layout (float offsets)
#define OX   0                          // x: [EPB][T_STEPS]  14336
#define OH1  (EPB * T_STEPS)            // h1: [2][Q]
#define OH2  (OH1 + 2 * Q)              // h2: [2][Q]
#define OPA  (OH2 + 2 * Q)              // pshA: [8][4][64] float4 = 8192 floats
#define OPB  (OPA + 8192)               // pshB: [8][4][64] float4 (3 used)
#define SMEM_FLOATS (OPB + 8192)        // 32512 floats = 130048 B

// Full fused matmul body for one element: L0 (h1) + L1 (h1 + h2), merged STS.128.
#define ELEM_BODY(HP1, HP2, E, PWp, EL)                                           \
    {                                                                             \
        const int eo = (E) * 16;                                                  \
        u64 aA, aB, bA, bB;                                                       \
        ulonglong2 p = (HP1)[eo + 0], r = (HP1)[eo + 1];                          \
        aA = mul2(p.x, w0A[0]); aB = mul2(p.x, w0B[0]);                           \
        bA = mul2(p.x, w1A[0]); bB = mul2(p.x, w1B[0]);                           \
        aA = fma2(p.y, w0A[1], aA); aB = fma2(p.y, w0B[1], aB);                   \
        aA = fma2(r.x, w0A[2], aA); aB = fma2(r.x, w0B[2], aB);                   \
        aA = fma2(r.y, w0A[3], aA); aB = fma2(r.y, w0B[3], aB);                   \
        bA = fma2(p.y, w1A[1], bA); bB = fma2(p.y, w1B[1], bB);                   \
        bA = fma2(r.x, w1A[2], bA); bB = fma2(r.x, w1B[2], bB);                   \
        bA = fma2(r.y, w1A[3], bA); bB = fma2(r.y, w1B[3], bB);                   \
        p = (HP1)[eo + 2]; r = (HP1)[eo + 3];                                     \
        aA = fma2(p.x, w0A[4], aA); aB = fma2(p.x, w0B[4], aB);                   \
        aA = fma2(p.y, w0A[5], aA); aB = fma2(p.y, w0B[5], aB);                   \
        aA = fma2(r.x, w0A[6], aA); aB = fma2(r.x, w0B[6], aB);                   \
        aA = fma2(r.y, w0A[7], aA); aB = fma2(r.y, w0B[7], aB);                   \
        bA = fma2(p.x, w1A[4], bA); bB = fma2(p.x, w1B[4], bB);                   \
        bA = fma2(p.y, w1A[5], bA); bB = fma2(p.y, w1B[5], bB);                   \
        bA = fma2(r.x, w1A[6], bA); bB = fma2(r.x, w1B[6], bB);                   \
        bA = fma2(r.y, w1A[7], bA); bB = fma2(r.y, w1B[7], bB);                   \
        float2 fa = unpack2(aA), fb = unpack2(aB);                                \
        float f0 = fa.x + fa.y, f1 = fb.x + fb.y;                                 \
        p = (HP2)[eo + 0]; r = (HP2)[eo + 1];                                     \
        bA = fma2(p.x, w1A[8],  bA); bB = fma2(p.x, w1B[8],  bB);                 \
        bA = fma2(p.y, w1A[9],  bA); bB = fma2(p.y, w1B[9],  bB);                 \
        bA = fma2(r.x, w1A[10], bA); bB = fma2(r.x, w1B[10], bB);                 \
        bA = fma2(r.y, w1A[11], bA); bB = fma2(r.y, w1B[11], bB);                 \
        p = (HP2)[eo + 2]; r = (HP2)[eo + 3];                                     \
        bA = fma2(p.x, w1A[12], bA); bB = fma2(p.x, w1B[12], bB);                 \
        bA = fma2(p.y, w1A[13], bA); bB = fma2(p.y, w1B[13], bB);                 \
        bA = fma2(r.x, w1A[14], bA); bB = fma2(r.x, w1B[14], bB);                 \
        bA = fma2(r.y, w1A[15], bA); bB = fma2(r.y, w1B[15], bB);                 \
        float2 ga = unpack2(bA), gb = unpack2(bB);                                \
        (PWp)[(EL) * 64] = make_float4(f0, f1, ga.x + ga.y, gb.x + gb.y);         \
    }

// Tail matmul (L1 only) for one element.
#define TAIL_ELEM(HP1, HP2, E, PWp, EL)                                           \
    {                                                                             \
        const int eo = (E) * 16;                                                  \
        u64 bA, bB;                                                               \
        ulonglong2 p = (HP1)[eo + 0], r = (HP1)[eo + 1];                          \
        bA = mul2(p.x, w1A[0]); bB = mul2(p.x, w1B[0]);                           \
        bA = fma2(p.y, w1A[1], bA); bB = fma2(p.y, w1B[1], bB);                   \
        bA = fma2(r.x, w1A[2], bA); bB = fma2(r.x, w1B[2], bB);                   \
        bA = fma2(r.y, w1A[3], bA); bB = fma2(r.y, w1B[3], bB);                   \
        p = (HP1)[eo + 2]; r = (HP1)[eo + 3];                                     \
        bA = fma2(p.x, w1A[4], bA); bB = fma2(p.x, w1B[4], bB);                   \
        bA = fma2(p.y, w1A[5], bA); bB = fma2(p.y, w1B[5], bB);                   \
        bA = fma2(r.x, w1A[6], bA); bB = fma2(r.x, w1B[6], bB);                   \
        bA = fma2(r.y, w1A[7], bA); bB = fma2(r.y, w1B[7], bB);                   \
        p = (HP2)[eo + 0]; r = (HP2)[eo + 1];                                     \
        bA = fma2(p.x, w1A[8],  bA); bB = fma2(p.x, w1B[8],  bB);                 \
        bA = fma2(p.y, w1A[9],  bA); bB = fma2(p.y, w1B[9],  bB);                 \
        bA = fma2(r.x, w1A[10], bA); bB = fma2(r.x, w1B[10], bB);                 \
        bA = fma2(r.y, w1A[11], bA); bB = fma2(r.y, w1B[11], bB);                 \
        p = (HP2)[eo + 2]; r = (HP2)[eo + 3];                                     \
        bA = fma2(p.x, w1A[12], bA); bB = fma2(p.x, w1B[12], bB);                 \
        bA = fma2(p.y, w1A[13], bA); bB = fma2(p.y, w1B[13], bB);                 \
        bA = fma2(r.x, w1A[14], bA); bB = fma2(r.x, w1B[14], bB);                 \
        bA = fma2(r.y, w1A[15], bA); bB = fma2(r.y, w1B[15], bB);                 \
        float2 ga = unpack2(bA), gb = unpack2(bB);                                \
        (PWp)[(EL) * 64] = make_float4(0.0f, 0.0f, ga.x + ga.y, gb.x + gb.y);     \
    }

// Activation tasks. ACT0 = task0 (L0 cell, or q==7's L1-e0 with xw zeroed).
#define ACT0(PRp, XV, CREF, HSp, SLOT)                                            \
    {                                                                             \
        float2 a0 = (PRp)[0 * SQ2], a1 = (PRp)[2 * SQ2];                          \
        float2 a2 = (PRp)[4 * SQ2], a3 = (PRp)[6 * SQ2];                          \
        float2 g0 = (PRp)[1 * SQ2], g1 = (PRp)[3 * SQ2];                          \
        float2 g2 = (PRp)[5 * SQ2], g3 = (PRp)[7 * SQ2];                          \
        float xv = (XV);                                                          \
        float pi = a0.x + a1.x + a2.x + a3.x + fmaf(xv, xwi, tbi);                \
        float pf = a0.y + a1.y + a2.y + a3.y + fmaf(xv, xwf, tbf);                \
        float pg = g0.x + g1.x + g2.x + g3.x + fmaf(xv, xwg, tbg);                \
        float po = g0.y + g1.y + g2.y + g3.y + fmaf(xv, xwo, tbo);                \
        float gi = sig_fast(pi), gf = sig_fast(pf);                               \
        float gg = tanh_fast(pg), go = sig_fast(po);                              \
        CREF = gf * CREF + gi * gg;                                               \
        (HSp)[(SLOT) * Q] = go * tanh_fast(CREF);                                 \
    }
#define ACT1(PRp, CREF, HSp, SLOT)                                                \
    {                                                                             \
        float2 a0 = (PRp)[0 * SQ2], a1 = (PRp)[2 * SQ2];                          \
        float2 a2 = (PRp)[4 * SQ2], a3 = (PRp)[6 * SQ2];                          \
        float2 g0 = (PRp)[1 * SQ2], g1 = (PRp)[3 * SQ2];                          \
        float2 g2 = (PRp)[5 * SQ2], g3 = (PRp)[7 * SQ2];                          \
        float pi = a0.x + a1.x + a2.x + a3.x + b1i;                               \
        float pf = a0.y + a1.y + a2.y + a3.y + b1f;                               \
        float pg = g0.x + g1.x + g2.x + g3.x + b1g;                               \
        float po = g0.y + g1.y + g2.y + g3.y + b1o;                               \
        float gi = sig_fast(pi), gf = sig_fast(pf);                               \
        float gg = tanh_fast(pg), go = sig_fast(po);                              \
        CREF = gf * CREF + gi * gg;                                               \
        (HSp)[(SLOT) * Q] = go * tanh_fast(CREF);                                 \
    }

__global__ void __launch_bounds__(NTHR, 1)
lstm_fused(const float* __restrict__ x,
           const float* __restrict__ Wih0, const float* __restrict__ Whh0,
           const float* __restrict__ bih0, const float* __restrict__ bhh0,
           const float* __restrict__ Wih1, const float* __restrict__ Whh1,
           const float* __restrict__ bih1, const float* __restrict__ bhh1,
           const float* __restrict__ fcW,  const float* __restrict__ fcb,
           float* __restrict__ out, int B)
{
    float*  xs   = smem_f + OX;
    float*  h1f  = smem_f + OH1;
    float*  h2f  = smem_f + OH2;
    float4* pshA = (float4*)(smem_f + OPA);
    float4* pshB = (float4*)(smem_f + OPB);

    const int tid = threadIdx.x;
    const int u   = tid & 63;
    const int gp  = (tid >> 6) & 1;
    const int s   = tid >> 7;
    const int q   = s * 2 + gp;          // 0..7, warp-uniform
    const int b0e = blockIdx.x * EPB;

    // ---- stage x rows ----
    for (int i = tid; i < EPB * T_STEPS / 4; i += NTHR) {
        int e = i / (T_STEPS / 4), c = i % (T_STEPS / 4);
        int be = b0e + e; if (be > B - 1) be = B - 1;
        ((float4*)xs)[i] = ((const float4*)(x + (size_t)be * T_STEPS))[c];
    }
    for (int i = tid; i < 2 * Q; i += NTHR) { h1f[i] = 0.0f; h2f[i] = 0.0f; }

    // ---- register weights (k-window [16s,16s+16)) ----
    const int rA = (gp * 2) * 64 + u, rB = (gp * 2 + 1) * 64 + u;
    const int k0 = s * 16;
    u64 w0A[8], w0B[8];
#pragma unroll
    for (int p = 0; p < 8; ++p) {
        w0A[p] = pack2(Whh0[rA * 64 + k0 + 2 * p], Whh0[rA * 64 + k0 + 2 * p + 1]);
        w0B[p] = pack2(Whh0[rB * 64 + k0 + 2 * p], Whh0[rB * 64 + k0 + 2 * p + 1]);
    }
    u64 w1A[16], w1B[16];
#pragma unroll
    for (int p = 0; p < 8; ++p) {
        w1A[p]     = pack2(Wih1[rA * 64 + k0 + 2 * p], Wih1[rA * 64 + k0 + 2 * p + 1]);
        w1B[p]     = pack2(Wih1[rB * 64 + k0 + 2 * p], Wih1[rB * 64 + k0 + 2 * p + 1]);
        w1A[8 + p] = pack2(Whh1[rA * 64 + k0 + 2 * p], Whh1[rA * 64 + k0 + 2 * p + 1]);
        w1B[8 + p] = pack2(Whh1[rB * 64 + k0 + 2 * p], Whh1[rB * 64 + k0 + 2 * p + 1]);
    }

    // ---- psh writer bases ----
    float4* pwA = pshA + q * 256 + u;
    float4* pwB = pshB + q * 256 + u;

    // ---- activation task state ----
    const bool t0L1 = (q == 7);
    const int  e0   = t0L1 ? 0 : q;
    // task0 read pointer (.xy for L0; .zw for q==7's L1-e0)
    const float2* pr0 =
        (q <= 3) ? (const float2*)pshA + (q * 64 + u) * 2
      : (q <= 6) ? (const float2*)pshB + ((q - 4) * 64 + u) * 2
                 : (const float2*)pshA + u * 2 + 1;
    float* hs0 = (t0L1 ? h2f : h1f) + e0 * HID + u;
    const float* xb0 = xs + e0 * T_STEPS;
    // task1: L1 element q+1 (valid q<=5), .zw half
    const float2* pr1 =
        (q <= 2) ? (const float2*)pshA + ((q + 1) * 64 + u) * 2 + 1
      : (q <= 5) ? (const float2*)pshB + ((q - 3) * 64 + u) * 2 + 1
                 : (const float2*)pshA + u * 2 + 1;   // dummy (guarded)
    float* hs1 = h2f + ((q <= 5) ? (q + 1) : 0) * HID + u;
    // region membership
    const bool inR1_0 = (q >= 4 && q <= 6);
    const bool inR1_1 = (q >= 3 && q <= 5);
    const bool inR2_0 = (q <= 3 || q == 7);
    const bool inR2_1 = (q <= 2);

    // biases / x-weights (task0 uses tb/xw; task1 uses b1)
    const float b1i = bih1[u] + bhh1[u],             b1f = bih1[64 + u] + bhh1[64 + u];
    const float b1g = bih1[128 + u] + bhh1[128 + u], b1o = bih1[192 + u] + bhh1[192 + u];
    const float tbi = t0L1 ? b1i : (bih0[u] + bhh0[u]);
    const float tbf = t0L1 ? b1f : (bih0[64 + u] + bhh0[64 + u]);
    const float tbg = t0L1 ? b1g : (bih0[128 + u] + bhh0[128 + u]);
    const float tbo = t0L1 ? b1o : (bih0[192 + u] + bhh0[192 + u]);
    const float xwi = t0L1 ? 0.0f : Wih0[u];
    const float xwf = t0L1 ? 0.0f : Wih0[64 + u];
    const float xwg = t0L1 ? 0.0f : Wih0[128 + u];
    const float xwo = t0L1 ? 0.0f : Wih0[192 + u];

    // h read bases (slot 0 / slot 1)
    const ulonglong2* hp1_0 = (const ulonglong2*)h1f + s * 4;
    const ulonglong2* hp1_1 = (const ulonglong2*)(h1f + Q) + s * 4;
    const ulonglong2* hp2_0 = (const ulonglong2*)h2f + s * 4;
    const ulonglong2* hp2_1 = (const ulonglong2*)(h2f + Q) + s * 4;

    float cA = 0.0f, cB = 0.0f;
    __syncthreads();

#pragma unroll 1
    for (int j = 0; j < T_STEPS; ++j) {
        const int rb = j & 1;
        const ulonglong2* hp1 = rb ? hp1_1 : hp1_0;
        const ulonglong2* hp2 = rb ? hp2_1 : hp2_0;

        // ===== R1: act_B(iter j-1) + matmul_A(iter j) =====
        if (inR1_0 && j >= 1) ACT0(pr0, xb0[j - 1], cA, hs0, rb)
        if (inR1_1 && j >= 2) ACT1(pr1, cB, hs1, rb)
        ELEM_BODY(hp1, hp2, 0, pwA, 0)
        ELEM_BODY(hp1, hp2, 1, pwA, 1)
        ELEM_BODY(hp1, hp2, 2, pwA, 2)
        ELEM_BODY(hp1, hp2, 3, pwA, 3)
        __syncthreads();

        // ===== R2: act_A(iter j) + matmul_B(iter j) =====
        if (inR2_0 && (!t0L1 || j >= 1)) ACT0(pr0, xb0[j], cA, hs0, rb ^ 1)
        if (inR2_1 && j >= 1) ACT1(pr1, cB, hs1, rb ^ 1)
        ELEM_BODY(hp1, hp2, 4, pwB, 0)
        ELEM_BODY(hp1, hp2, 5, pwB, 1)
        ELEM_BODY(hp1, hp2, 6, pwB, 2)
        __syncthreads();
    }

    // ===== epilogue =====
    // E1: act_B(iter T-1): h1_B[T-1], h2_B[T-2] -> slot 0 (T even)
    if (inR1_0) ACT0(pr0, xb0[T_STEPS - 1], cA, hs0, 0)
    if (inR1_1) ACT1(pr1, cB, hs1, 0)
    __syncthreads();
    // E2: tail matmul L1(T-1), reads h1[T-1], h2[T-2] (slot 0)
    TAIL_ELEM(hp1_0, hp2_0, 0, pwA, 0)
    TAIL_ELEM(hp1_0, hp2_0, 1, pwA, 1)
    TAIL_ELEM(hp1_0, hp2_0, 2, pwA, 2)
    TAIL_ELEM(hp1_0, hp2_0, 3, pwA, 3)
    TAIL_ELEM(hp1_0, hp2_0, 4, pwB, 0)
    TAIL_ELEM(hp1_0, hp2_0, 5, pwB, 1)
    TAIL_ELEM(hp1_0, hp2_0, 6, pwB, 2)
    __syncthreads();
    // E3: final L1(T-1) activations -> h2[T-1] in slot 1
    if (t0L1)   ACT0(pr0, 0.0f, cA, hs0, 1)
    if (q <= 5) ACT1(pr1, cB, hs1, 1)
    __syncthreads();

    // ---- final FC: h2[T-1] in slot 1 ----
    if (tid < EPB * 32) {
        const int e = tid >> 5, lane = tid & 31;
        const float* h2l = h2f + Q + e * HID;
        float acc = h2l[lane] * fcW[lane] + h2l[32 + lane] * fcW[32 + lane];
#pragma unroll
        for (int o = 16; o > 0; o >>= 1)
            acc += __shfl_down_sync(0xFFFFFFFFu, acc, o);
        if (lane == 0) {
            int be = b0e + e; if (be > B - 1) be = B - 1;
            out[be] = acc + fcb[0];
        }
    }
}

extern "C" void kernel_launch(void* const* d_in, const int* in_sizes, int n_in,
                              void* d_out, int out_size)
{
    const float* x    = (const float*)d_in[0];
    const float* Wih0 = (const float*)d_in[1];
    const float* Whh0 = (const float*)d_in[2];
    const float* bih0 = (const float*)d_in[3];
    const float* bhh0 = (const float*)d_in[4];
    const float* Wih1 = (const float*)d_in[5];
    const float* Whh1 = (const float*)d_in[6];
    const float* bih1 = (const float*)d_in[7];
    const float* bhh1 = (const float*)d_in[8];
    const float* fcW  = (const float*)d_in[9];
    const float* fcb  = (const float*)d_in[10];
    float* out = (float*)d_out;

    int B = in_sizes[0] / T_STEPS;
    if (B < 1) B = 1;
    int blocks = (B + EPB - 1) / EPB;

    const int smem_bytes = SMEM_FLOATS * 4;
    cudaFuncSetAttribute(lstm_fused, cudaFuncAttributeMaxDynamicSharedMemorySize,
                         smem_bytes);

    lstm_fused<<<blocks, NTHR, smem_bytes>>>(x, Wih0, Whh0, bih0, bhh0,
                                             Wih1, Whh1, bih1, bhh1,
                                             fcW, fcb, out, B);
}

// round 15
// speedup vs baseline: 1.0192x; 1.0192x over previous
#include <cuda_runtime.h>
#include <cstdint>

#define T_STEPS 2048
#define HID 64
#define EPB 7
#define NTHR 512
#define Q (EPB * HID)            // 448 floats per h slot
#define SQ2 896                  // psh q-slot stride in float2 units (448 float4)

typedef unsigned long long u64;

// ---------- f32x2 packed math ----------
__device__ __forceinline__ u64 fma2(u64 a, u64 b, u64 c) {
    u64 d; asm("fma.rn.f32x2 %0, %1, %2, %3;" : "=l"(d) : "l"(a), "l"(b), "l"(c)); return d;
}
__device__ __forceinline__ u64 mul2(u64 a, u64 b) {
    u64 d; asm("mul.rn.f32x2 %0, %1, %2;" : "=l"(d) : "l"(a), "l"(b)); return d;
}
__device__ __forceinline__ u64 pack2(float lo, float hi) {
    u64 d; asm("mov.b64 %0, {%1, %2};" : "=l"(d) : "f"(lo), "f"(hi)); return d;
}
__device__ __forceinline__ float2 unpack2(u64 v) {
    float a, b; asm("mov.b64 {%0, %1}, %2;" : "=f"(a), "=f"(b) : "l"(v));
    return make_float2(a, b);
}

// ---------- fast activations: MUFU.TANH ----------
__device__ __forceinline__ float tanh_fast(float x) {
    float r; asm("tanh.approx.f32 %0, %1;" : "=f"(r) : "f"(x)); return r;
}
__device__ __forceinline__ float sig_fast(float x) {
    return fmaf(tanh_fast(0.5f * x), 0.5f, 0.5f);
}

extern __shared__ float smem_f[];
// SMEM layout (float offsets)
#define OX   0                          // x: [EPB][T_STEPS]
#define OH1  (EPB * T_STEPS)            // h1: [2][Q]
#define OH2  (OH1 + 2 * Q)              // h2: [2][Q]
#define OP   (OH2 + 2 * Q)              // psh: [8][EPB][HID] float4 = 14336 floats
#define SMEM_FLOATS (OP + 4 * 8 * Q)    // 121856 B

// Phase-1 body: uniform for ALL threads — mul2 starts, single merged STS.128.
#define PHASE1_LOOP(HP1, HP2)                                                     \
    _Pragma("unroll")                                                             \
    for (int e = 0; e < EPB; ++e) {                                               \
        const int eo = e * 16;                                                    \
        u64 aA, aB, bA, bB;                                                       \
        ulonglong2 p = (HP1)[eo + 0], r = (HP1)[eo + 1];                          \
        aA = mul2(p.x, w0A[0]); aB = mul2(p.x, w0B[0]);                           \
        bA = mul2(p.x, w1A[0]); bB = mul2(p.x, w1B[0]);                           \
        aA = fma2(p.y, w0A[1], aA); aB = fma2(p.y, w0B[1], aB);                   \
        aA = fma2(r.x, w0A[2], aA); aB = fma2(r.x, w0B[2], aB);                   \
        aA = fma2(r.y, w0A[3], aA); aB = fma2(r.y, w0B[3], aB);                   \
        bA = fma2(p.y, w1A[1], bA); bB = fma2(p.y, w1B[1], bB);                   \
        bA = fma2(r.x, w1A[2], bA); bB = fma2(r.x, w1B[2], bB);                   \
        bA = fma2(r.y, w1A[3], bA); bB = fma2(r.y, w1B[3], bB);                   \
        p = (HP1)[eo + 2]; r = (HP1)[eo + 3];                                     \
        aA = fma2(p.x, w0A[4], aA); aB = fma2(p.x, w0B[4], aB);                   \
        aA = fma2(p.y, w0A[5], aA); aB = fma2(p.y, w0B[5], aB);                   \
        aA = fma2(r.x, w0A[6], aA); aB = fma2(r.x, w0B[6], aB);                   \
        aA = fma2(r.y, w0A[7], aA); aB = fma2(r.y, w0B[7], aB);                   \
        bA = fma2(p.x, w1A[4], bA); bB = fma2(p.x, w1B[4], bB);                   \
        bA = fma2(p.y, w1A[5], bA); bB = fma2(p.y, w1B[5], bB);                   \
        bA = fma2(r.x, w1A[6], bA); bB = fma2(r.x, w1B[6], bB);                   \
        bA = fma2(r.y, w1A[7], bA); bB = fma2(r.y, w1B[7], bB);                   \
        float2 fa = unpack2(aA), fb = unpack2(aB);                                \
        float f0 = fa.x + fa.y, f1 = fb.x + fb.y;                                 \
        p = (HP2)[eo + 0]; r = (HP2)[eo + 1];                                     \
        bA = fma2(p.x, w1A[8],  bA); bB = fma2(p.x, w1B[8],  bB);                 \
        bA = fma2(p.y, w1A[9],  bA); bB = fma2(p.y, w1B[9],  bB);                 \
        bA = fma2(r.x, w1A[10], bA); bB = fma2(r.x, w1B[10], bB);                 \
        bA = fma2(r.y, w1A[11], bA); bB = fma2(r.y, w1B[11], bB);                 \
        p = (HP2)[eo + 2]; r = (HP2)[eo + 3];                                     \
        bA = fma2(p.x, w1A[12], bA); bB = fma2(p.x, w1B[12], bB);                 \
        bA = fma2(p.y, w1A[13], bA); bB = fma2(p.y, w1B[13], bB);                 \
        bA = fma2(r.x, w1A[14], bA); bB = fma2(r.x, w1B[14], bB);                 \
        bA = fma2(r.y, w1A[15], bA); bB = fma2(r.y, w1B[15], bB);                 \
        float2 ga = unpack2(bA), gb = unpack2(bB);                                \
        pw[e * HID] = make_float4(f0, f1, ga.x + ga.y, gb.x + gb.y);              \
    }

__global__ void __launch_bounds__(NTHR, 1)
lstm_fused(const float* __restrict__ x,
           const float* __restrict__ Wih0, const float* __restrict__ Whh0,
           const float* __restrict__ bih0, const float* __restrict__ bhh0,
           const float* __restrict__ Wih1, const float* __restrict__ Whh1,
           const float* __restrict__ bih1, const float* __restrict__ bhh1,
           const float* __restrict__ fcW,  const float* __restrict__ fcb,
           float* __restrict__ out, int B)
{
    float*  xs   = smem_f + OX;
    float*  h1f  = smem_f + OH1;
    float*  h2f  = smem_f + OH2;
    float4* psh  = (float4*)(smem_f + OP);

    const int tid = threadIdx.x;
    const int u   = tid & 63;
    const int gp  = (tid >> 6) & 1;
    const int s   = tid >> 7;
    const int q   = s * 2 + gp;          // 0..7, warp-uniform
    const int b0e = blockIdx.x * EPB;

    // ---- stage x rows ----
    for (int i = tid; i < EPB * T_STEPS / 4; i += NTHR) {
        int e = i / (T_STEPS / 4), c = i % (T_STEPS / 4);
        int be = b0e + e; if (be > B - 1) be = B - 1;
        ((float4*)xs)[i] = ((const float4*)(x + (size_t)be * T_STEPS))[c];
    }
    for (int i = tid; i < 2 * Q; i += NTHR) { h1f[i] = 0.0f; h2f[i] = 0.0f; }

    // ---- register weights (k-window [16s,16s+16) for BOTH layers) ----
    const int rA = (gp * 2) * 64 + u, rB = (gp * 2 + 1) * 64 + u;
    const int k0 = s * 16;
    u64 w0A[8], w0B[8];
#pragma unroll
    for (int p = 0; p < 8; ++p) {
        w0A[p] = pack2(Whh0[rA * 64 + k0 + 2 * p], Whh0[rA * 64 + k0 + 2 * p + 1]);
        w0B[p] = pack2(Whh0[rB * 64 + k0 + 2 * p], Whh0[rB * 64 + k0 + 2 * p + 1]);
    }
    u64 w1A[16], w1B[16];
#pragma unroll
    for (int p = 0; p < 8; ++p) {
        w1A[p]     = pack2(Wih1[rA * 64 + k0 + 2 * p], Wih1[rA * 64 + k0 + 2 * p + 1]);
        w1B[p]     = pack2(Wih1[rB * 64 + k0 + 2 * p], Wih1[rB * 64 + k0 + 2 * p + 1]);
        w1A[8 + p] = pack2(Whh1[rA * 64 + k0 + 2 * p], Whh1[rA * 64 + k0 + 2 * p + 1]);
        w1B[8 + p] = pack2(Whh1[rB * 64 + k0 + 2 * p], Whh1[rB * 64 + k0 + 2 * p + 1]);
    }

    float4* pw = psh + q * Q + u;        // merged writer base (Q float4 per q-slot)

    const bool t0L1 = (q == 7);
    const int  e0   = t0L1 ? 0 : q;
    // task0: L0 cells read .xy half; q==7's L1-e0 reads .zw half
    const float2* pr0 = (const float2*)psh + 2 * (e0 * HID + u) + (t0L1 ? 1 : 0);
    float*        hs0 = (t0L1 ? h2f : h1f) + e0 * HID + u;
    const float*  xb0 = xs + e0 * T_STEPS;
    const bool has1 = (q < 6);
    const int  e1   = has1 ? (q + 1) : 0;
    const float2* pr1 = (const float2*)psh + 2 * (e1 * HID + u) + 1;   // .zw half
    float*        hs1 = h2f + e1 * HID + u;

    // ---- phase-2 activation constants (per-thread registers) ----
    const float b1i = bih1[u] + bhh1[u],             b1f = bih1[64 + u] + bhh1[64 + u];
    const float b1g = bih1[128 + u] + bhh1[128 + u], b1o = bih1[192 + u] + bhh1[192 + u];
    const float tbi = t0L1 ? b1i : (bih0[u] + bhh0[u]);
    const float tbf = t0L1 ? b1f : (bih0[64 + u] + bhh0[64 + u]);
    const float tbg = t0L1 ? b1g : (bih0[128 + u] + bhh0[128 + u]);
    const float tbo = t0L1 ? b1o : (bih0[192 + u] + bhh0[192 + u]);
    const float xwi = t0L1 ? 0.0f : Wih0[u];
    const float xwf = t0L1 ? 0.0f : Wih0[64 + u];
    const float xwg = t0L1 ? 0.0f : Wih0[128 + u];
    const float xwo = t0L1 ? 0.0f : Wih0[192 + u];

    // phase-1 read bases for both parities (pointer swap)
    const ulonglong2* hp1_0 = (const ulonglong2*)h1f + s * 4;
    const ulonglong2* hp1_1 = (const ulonglong2*)(h1f + Q) + s * 4;
    const ulonglong2* hp2_0 = (const ulonglong2*)h2f + s * 4;
    const ulonglong2* hp2_1 = (const ulonglong2*)(h2f + Q) + s * 4;

    float cA = 0.0f, cB = 0.0f;
    __syncthreads();

#pragma unroll 1
    for (int j = 0; j < T_STEPS; ++j) {
        const int rb = j & 1;
        const ulonglong2* hp1 = rb ? hp1_1 : hp1_0;
        const ulonglong2* hp2 = rb ? hp2_1 : hp2_0;

        // ========== phase 1 (single uniform body, merged STS.128) ==========
        PHASE1_LOOP(hp1, hp2)
        __syncthreads();

        // ========== phase 2 (bias + x*w folded, branch-free) ==========
        const int wo = (rb ^ 1) * Q;
        const bool act0 = t0L1 ? (j > 0) : true;
        if (act0) {
            float2 a0 = pr0[0 * SQ2], a1 = pr0[2 * SQ2], a2 = pr0[4 * SQ2], a3 = pr0[6 * SQ2];
            float2 g0 = pr0[1 * SQ2], g1 = pr0[3 * SQ2], g2 = pr0[5 * SQ2], g3 = pr0[7 * SQ2];
            float xv = xb0[j];
            float pi = a0.x + a1.x + a2.x + a3.x + fmaf(xv, xwi, tbi);
            float pf = a0.y + a1.y + a2.y + a3.y + fmaf(xv, xwf, tbf);
            float pg = g0.x + g1.x + g2.x + g3.x + fmaf(xv, xwg, tbg);
            float po = g0.y + g1.y + g2.y + g3.y + fmaf(xv, xwo, tbo);
            float gi = sig_fast(pi), gf = sig_fast(pf);
            float gg = tanh_fast(pg), go = sig_fast(po);
            cA = gf * cA + gi * gg;
            hs0[wo] = go * tanh_fast(cA);
        }
        if (has1 && j > 0) {
            float2 a0 = pr1[0 * SQ2], a1 = pr1[2 * SQ2], a2 = pr1[4 * SQ2], a3 = pr1[6 * SQ2];
            float2 g0 = pr1[1 * SQ2], g1 = pr1[3 * SQ2], g2 = pr1[5 * SQ2], g3 = pr1[7 * SQ2];
            float pi = a0.x + a1.x + a2.x + a3.x + b1i;
            float pf = a0.y + a1.y + a2.y + a3.y + b1f;
            float pg = g0.x + g1.x + g2.x + g3.x + b1g;
            float po = g0.y + g1.y + g2.y + g3.y + b1o;
            float gi = sig_fast(pi), gf = sig_fast(pf);
            float gg = tanh_fast(pg), go = sig_fast(po);
            cB = gf * cB + gi * gg;
            hs1[wo] = go * tanh_fast(cB);
        }
        __syncthreads();
    }

    // ========== tail: L1 step T-1 (h1[T-1], h2[T-2] in slot 0) ==========
    {
        const ulonglong2* hp1 = hp1_0;
        const ulonglong2* hp2 = hp2_0;
#pragma unroll
        for (int e = 0; e < EPB; ++e) {
            const int eo = e * 16;
            u64 bA, bB;
            ulonglong2 p = hp1[eo + 0], r = hp1[eo + 1];
            bA = mul2(p.x, w1A[0]); bB = mul2(p.x, w1B[0]);
            bA = fma2(p.y, w1A[1], bA); bB = fma2(p.y, w1B[1], bB);
            bA = fma2(r.x, w1A[2], bA); bB = fma2(r.x, w1B[2], bB);
            bA = fma2(r.y, w1A[3], bA); bB = fma2(r.y, w1B[3], bB);
            p = hp1[eo + 2]; r = hp1[eo + 3];
            bA = fma2(p.x, w1A[4], bA); bB = fma2(p.x, w1B[4], bB);
            bA = fma2(p.y, w1A[5], bA); bB = fma2(p.y, w1B[5], bB);
            bA = fma2(r.x, w1A[6], bA); bB = fma2(r.x, w1B[6], bB);
            bA = fma2(r.y, w1A[7], bA); bB = fma2(r.y, w1B[7], bB);
            p = hp2[eo + 0]; r = hp2[eo + 1];
            bA = fma2(p.x, w1A[8],  bA); bB = fma2(p.x, w1B[8],  bB);
            bA = fma2(p.y, w1A[9],  bA); bB = fma2(p.y, w1B[9],  bB);
            bA = fma2(r.x, w1A[10], bA); bB = fma2(r.x, w1B[10], bB);
            bA = fma2(r.y, w1A[11], bA); bB = fma2(r.y, w1B[11], bB);
            p = hp2[eo + 2]; r = hp2[eo + 3];
            bA = fma2(p.x, w1A[12], bA); bB = fma2(p.x, w1B[12], bB);
            bA = fma2(p.y, w1A[13], bA); bB = fma2(p.y, w1B[13], bB);
            bA = fma2(r.x, w1A[14], bA); bB = fma2(r.x, w1B[14], bB);
            bA = fma2(r.y, w1A[15], bA); bB = fma2(r.y, w1B[15], bB);
            float2 ga = unpack2(bA), gb = unpack2(bB);
            pw[e * HID] = make_float4(0.0f, 0.0f, ga.x + ga.y, gb.x + gb.y);
        }
    }
    __syncthreads();
    {
        if (t0L1) {
            float2 a0 = pr0[0 * SQ2], a1 = pr0[2 * SQ2], a2 = pr0[4 * SQ2], a3 = pr0[6 * SQ2];
            float2 g0 = pr0[1 * SQ2], g1 = pr0[3 * SQ2], g2 = pr0[5 * SQ2], g3 = pr0[7 * SQ2];
            float pi = a0.x + a1.x + a2.x + a3.x + b1i;
            float pf = a0.y + a1.y + a2.y + a3.y + b1f;
            float pg = g0.x + g1.x + g2.x + g3.x + b1g;
            float po = g0.y + g1.y + g2.y + g3.y + b1o;
            float gi = sig_fast(pi), gf = sig_fast(pf);
            float gg = tanh_fast(pg), go = sig_fast(po);
            cA = gf * cA + gi * gg;
            hs0[Q] = go * tanh_fast(cA);
        }
        if (has1) {
            float2 a0 = pr1[0 * SQ2], a1 = pr1[2 * SQ2], a2 = pr1[4 * SQ2], a3 = pr1[6 * SQ2];
            float2 g0 = pr1[1 * SQ2], g1 = pr1[3 * SQ2], g2 = pr1[5 * SQ2], g3 = pr1[7 * SQ2];
            float pi = a0.x + a1.x + a2.x + a3.x + b1i;
            float pf = a0.y + a1.y + a2.y + a3.y + b1f;
            float pg = g0.x + g1.x + g2.x + g3.x + b1g;
            float po = g0.y + g1.y + g2.y + g3.y + b1o;
            float gi = sig_fast(pi), gf = sig_fast(pf);
            float gg = tanh_fast(pg), go = sig_fast(po);
            cB = gf * cB + gi * gg;
            hs1[Q] = go * tanh_fast(cB);
        }
    }
    __syncthreads();

    // ---- final FC: h2[T-1] in slot 1 ----
    if (tid < EPB * 32) {
        const int e = tid >> 5, lane = tid & 31;
        const float* h2l = h2f + Q + e * HID;
        float acc = h2l[lane] * fcW[lane] + h2l[32 + lane] * fcW[32 + lane];
#pragma unroll
        for (int o = 16; o > 0; o >>= 1)
            acc += __shfl_down_sync(0xFFFFFFFFu, acc, o);
        if (lane == 0) {
            int be = b0e + e; if (be > B - 1) be = B - 1;
            out[be] = acc + fcb[0];
        }
    }
}

extern "C" void kernel_launch(void* const* d_in, const int* in_sizes, int n_in,
                              void* d_out, int out_size)
{
    const float* x    = (const float*)d_in[0];
    const float* Wih0 = (const float*)d_in[1];
    const float* Whh0 = (const float*)d_in[2];
    const float* bih0 = (const float*)d_in[3];
    const float* bhh0 = (const float*)d_in[4];
    const float* Wih1 = (const float*)d_in[5];
    const float* Whh1 = (const float*)d_in[6];
    const float* bih1 = (const float*)d_in[7];
    const float* bhh1 = (const float*)d_in[8];
    const float* fcW  = (const float*)d_in[9];
    const float* fcb  = (const float*)d_in[10];
    float* out = (float*)d_out;

    int B = in_sizes[0] / T_STEPS;
    if (B < 1) B = 1;
    int blocks = (B + EPB - 1) / EPB;

    const int smem_bytes = SMEM_FLOATS * 4;
    cudaFuncSetAttribute(lstm_fused, cudaFuncAttributeMaxDynamicSharedMemorySize,
                         smem_bytes);

    lstm_fused<<<blocks, NTHR, smem_bytes>>>(x, Wih0, Whh0, bih0, bhh0,
                                             Wih1, Whh1, bih1, bhh1,
                                             fcW, fcb, out, B);
}

// round 16
// speedup vs baseline: 1.1016x; 1.0809x over previous
#include <cuda_runtime.h>
#include <cstdint>

#define T_STEPS 2048
#define HID 64
#define EPB 7
#define NTHR 512
#define Q (EPB * HID)            // 448: h-slot floats AND psh q-slot stride (float2)

typedef unsigned long long u64;

// ---------- f32x2 packed math ----------
__device__ __forceinline__ u64 fma2(u64 a, u64 b, u64 c) {
    u64 d; asm("fma.rn.f32x2 %0, %1, %2, %3;" : "=l"(d) : "l"(a), "l"(b), "l"(c)); return d;
}
__device__ __forceinline__ u64 mul2(u64 a, u64 b) {
    u64 d; asm("mul.rn.f32x2 %0, %1, %2;" : "=l"(d) : "l"(a), "l"(b)); return d;
}
__device__ __forceinline__ u64 pack2(float lo, float hi) {
    u64 d; asm("mov.b64 %0, {%1, %2};" : "=l"(d) : "f"(lo), "f"(hi)); return d;
}
__device__ __forceinline__ float2 unpack2(u64 v) {
    float a, b; asm("mov.b64 {%0, %1}, %2;" : "=f"(a), "=f"(b) : "l"(v));
    return make_float2(a, b);
}

// ---------- fast activations: MUFU.TANH ----------
__device__ __forceinline__ float tanh_fast(float x) {
    float r; asm("tanh.approx.f32 %0, %1;" : "=f"(r) : "f"(x)); return r;
}
__device__ __forceinline__ float sig_fast(float x) {
    return fmaf(tanh_fast(0.5f * x), 0.5f, 0.5f);
}

extern __shared__ float smem_f[];
// SMEM layout (float offsets) — identical to the 5225us kernel
#define OX   0                          // x: [EPB][T_STEPS]
#define OH1  (EPB * T_STEPS)            // h1: [2][Q]
#define OH2  (OH1 + 2 * Q)              // h2: [2][Q]
#define OP0  (OH2 + 2 * Q)              // psh0: [8][Q] float2
#define OP1  (OP0 + 2 * 8 * Q)          // psh1: [8][Q] float2
#define SMEM_FLOATS (OP1 + 2 * 8 * Q)   // 121856 B

// Phase-1 body: uniform for ALL threads. h1 scalars feed QUADS {aA,aB,bA,bB}
// (maximizes operand-reuse-cache runs -> FFMA2 rt ~2 instead of ~2.5-3).
// Accumulator chains keep the exact same arithmetic order as before (bit-identical).
#define PHASE1_LOOP(HP1, HP2)                                                     \
    _Pragma("unroll")                                                             \
    for (int e = 0; e < EPB; ++e) {                                               \
        const int eo = e * 16;                                                    \
        u64 aA, aB, bA, bB;                                                       \
        ulonglong2 p = (HP1)[eo + 0], r = (HP1)[eo + 1];                          \
        aA = mul2(p.x, w0A[0]);      aB = mul2(p.x, w0B[0]);                      \
        bA = mul2(p.x, w1A[0]);      bB = mul2(p.x, w1B[0]);                      \
        aA = fma2(p.y, w0A[1], aA);  aB = fma2(p.y, w0B[1], aB);                  \
        bA = fma2(p.y, w1A[1], bA);  bB = fma2(p.y, w1B[1], bB);                  \
        aA = fma2(r.x, w0A[2], aA);  aB = fma2(r.x, w0B[2], aB);                  \
        bA = fma2(r.x, w1A[2], bA);  bB = fma2(r.x, w1B[2], bB);                  \
        aA = fma2(r.y, w0A[3], aA);  aB = fma2(r.y, w0B[3], aB);                  \
        bA = fma2(r.y, w1A[3], bA);  bB = fma2(r.y, w1B[3], bB);                  \
        p = (HP1)[eo + 2]; r = (HP1)[eo + 3];                                     \
        aA = fma2(p.x, w0A[4], aA);  aB = fma2(p.x, w0B[4], aB);                  \
        bA = fma2(p.x, w1A[4], bA);  bB = fma2(p.x, w1B[4], bB);                  \
        aA = fma2(p.y, w0A[5], aA);  aB = fma2(p.y, w0B[5], aB);                  \
        bA = fma2(p.y, w1A[5], bA);  bB = fma2(p.y, w1B[5], bB);                  \
        aA = fma2(r.x, w0A[6], aA);  aB = fma2(r.x, w0B[6], aB);                  \
        bA = fma2(r.x, w1A[6], bA);  bB = fma2(r.x, w1B[6], bB);                  \
        aA = fma2(r.y, w0A[7], aA);  aB = fma2(r.y, w0B[7], aB);                  \
        bA = fma2(r.y, w1A[7], bA);  bB = fma2(r.y, w1B[7], bB);                  \
        {                                                                         \
            float2 fa = unpack2(aA), fb = unpack2(aB);                            \
            pw0[e * HID] = make_float2(fa.x + fa.y, fb.x + fb.y);                 \
        }                                                                         \
        p = (HP2)[eo + 0]; r = (HP2)[eo + 1];                                     \
        bA = fma2(p.x, w1A[8],  bA); bB = fma2(p.x, w1B[8],  bB);                 \
        bA = fma2(p.y, w1A[9],  bA); bB = fma2(p.y, w1B[9],  bB);                 \
        bA = fma2(r.x, w1A[10], bA); bB = fma2(r.x, w1B[10], bB);                 \
        bA = fma2(r.y, w1A[11], bA); bB = fma2(r.y, w1B[11], bB);                 \
        p = (HP2)[eo + 2]; r = (HP2)[eo + 3];                                     \
        bA = fma2(p.x, w1A[12], bA); bB = fma2(p.x, w1B[12], bB);                 \
        bA = fma2(p.y, w1A[13], bA); bB = fma2(p.y, w1B[13], bB);                 \
        bA = fma2(r.x, w1A[14], bA); bB = fma2(r.x, w1B[14], bB);                 \
        bA = fma2(r.y, w1A[15], bA); bB = fma2(r.y, w1B[15], bB);                 \
        {                                                                         \
            float2 ga = unpack2(bA), gb = unpack2(bB);                            \
            pw1[e * HID] = make_float2(ga.x + ga.y, gb.x + gb.y);                 \
        }                                                                         \
    }

__global__ void __launch_bounds__(NTHR, 1)
lstm_fused(const float* __restrict__ x,
           const float* __restrict__ Wih0, const float* __restrict__ Whh0,
           const float* __restrict__ bih0, const float* __restrict__ bhh0,
           const float* __restrict__ Wih1, const float* __restrict__ Whh1,
           const float* __restrict__ bih1, const float* __restrict__ bhh1,
           const float* __restrict__ fcW,  const float* __restrict__ fcb,
           float* __restrict__ out, int B)
{
    float*  xs   = smem_f + OX;
    float*  h1f  = smem_f + OH1;
    float*  h2f  = smem_f + OH2;
    float2* psh0 = (float2*)(smem_f + OP0);
    float2* psh1 = (float2*)(smem_f + OP1);

    const int tid = threadIdx.x;
    const int u   = tid & 63;
    const int gp  = (tid >> 6) & 1;
    const int s   = tid >> 7;
    const int q   = s * 2 + gp;          // 0..7, warp-uniform
    const int b0e = blockIdx.x * EPB;

    // ---- stage x rows ----
    for (int i = tid; i < EPB * T_STEPS / 4; i += NTHR) {
        int e = i / (T_STEPS / 4), c = i % (T_STEPS / 4);
        int be = b0e + e; if (be > B - 1) be = B - 1;
        ((float4*)xs)[i] = ((const float4*)(x + (size_t)be * T_STEPS))[c];
    }
    for (int i = tid; i < 2 * Q; i += NTHR) { h1f[i] = 0.0f; h2f[i] = 0.0f; }

    // ---- register weights (k-window [16s,16s+16) for BOTH layers) ----
    const int rA = (gp * 2) * 64 + u, rB = (gp * 2 + 1) * 64 + u;
    const int k0 = s * 16;
    u64 w0A[8], w0B[8];
#pragma unroll
    for (int p = 0; p < 8; ++p) {
        w0A[p] = pack2(Whh0[rA * 64 + k0 + 2 * p], Whh0[rA * 64 + k0 + 2 * p + 1]);
        w0B[p] = pack2(Whh0[rB * 64 + k0 + 2 * p], Whh0[rB * 64 + k0 + 2 * p + 1]);
    }
    u64 w1A[16], w1B[16];
#pragma unroll
    for (int p = 0; p < 8; ++p) {
        w1A[p]     = pack2(Wih1[rA * 64 + k0 + 2 * p], Wih1[rA * 64 + k0 + 2 * p + 1]);
        w1B[p]     = pack2(Wih1[rB * 64 + k0 + 2 * p], Wih1[rB * 64 + k0 + 2 * p + 1]);
        w1A[8 + p] = pack2(Whh1[rA * 64 + k0 + 2 * p], Whh1[rA * 64 + k0 + 2 * p + 1]);
        w1B[8 + p] = pack2(Whh1[rB * 64 + k0 + 2 * p], Whh1[rB * 64 + k0 + 2 * p + 1]);
    }

    float2* pw0 = psh0 + q * Q + u;
    float2* pw1 = psh1 + q * Q + u;
    const bool t0L1 = (q == 7);
    const int  e0   = t0L1 ? 0 : q;
    const float2* pr0 = (t0L1 ? psh1 : psh0) + e0 * HID + u;
    float*        hs0 = (t0L1 ? h2f : h1f) + e0 * HID + u;
    const float*  xb0 = xs + e0 * T_STEPS;
    const bool has1 = (q < 6);
    const int  e1   = has1 ? (q + 1) : 0;
    const float2* pr1 = psh1 + e1 * HID + u;
    float*        hs1 = h2f + e1 * HID + u;

    // ---- phase-2 activation constants (per-thread registers, branch-free) ----
    const float b1i = bih1[u] + bhh1[u],             b1f = bih1[64 + u] + bhh1[64 + u];
    const float b1g = bih1[128 + u] + bhh1[128 + u], b1o = bih1[192 + u] + bhh1[192 + u];
    const float tbi = t0L1 ? b1i : (bih0[u] + bhh0[u]);
    const float tbf = t0L1 ? b1f : (bih0[64 + u] + bhh0[64 + u]);
    const float tbg = t0L1 ? b1g : (bih0[128 + u] + bhh0[128 + u]);
    const float tbo = t0L1 ? b1o : (bih0[192 + u] + bhh0[192 + u]);
    const float xwi = t0L1 ? 0.0f : Wih0[u];
    const float xwf = t0L1 ? 0.0f : Wih0[64 + u];
    const float xwg = t0L1 ? 0.0f : Wih0[128 + u];
    const float xwo = t0L1 ? 0.0f : Wih0[192 + u];

    // phase-1 read bases for both parities (pointer swap)
    const ulonglong2* hp1_0 = (const ulonglong2*)h1f + s * 4;
    const ulonglong2* hp1_1 = (const ulonglong2*)(h1f + Q) + s * 4;
    const ulonglong2* hp2_0 = (const ulonglong2*)h2f + s * 4;
    const ulonglong2* hp2_1 = (const ulonglong2*)(h2f + Q) + s * 4;

    float cA = 0.0f, cB = 0.0f;
    __syncthreads();

#pragma unroll 1
    for (int j = 0; j < T_STEPS; ++j) {
        const int rb = j & 1;
        const ulonglong2* hp1 = rb ? hp1_1 : hp1_0;
        const ulonglong2* hp2 = rb ? hp2_1 : hp2_0;

        // ========== phase 1 (single uniform body, quad-reuse ordering) ==========
        PHASE1_LOOP(hp1, hp2)
        __syncthreads();

        // ========== phase 2 (bias + x*w folded, branch-free) ==========
        const int wo = (rb ^ 1) * Q;
        const bool act0 = t0L1 ? (j > 0) : true;
        if (act0) {
            float xv = xb0[j];      // hoisted: overlaps its LDS latency with psh loads
            float2 a0 = pr0[0 * Q], a1 = pr0[2 * Q], a2 = pr0[4 * Q], a3 = pr0[6 * Q];
            float2 g0 = pr0[1 * Q], g1 = pr0[3 * Q], g2 = pr0[5 * Q], g3 = pr0[7 * Q];
            float pi = a0.x + a1.x + a2.x + a3.x + fmaf(xv, xwi, tbi);
            float pf = a0.y + a1.y + a2.y + a3.y + fmaf(xv, xwf, tbf);
            float pg = g0.x + g1.x + g2.x + g3.x + fmaf(xv, xwg, tbg);
            float po = g0.y + g1.y + g2.y + g3.y + fmaf(xv, xwo, tbo);
            float gi = sig_fast(pi), gf = sig_fast(pf);
            float gg = tanh_fast(pg), go = sig_fast(po);
            cA = gf * cA + gi * gg;
            hs0[wo] = go * tanh_fast(cA);
        }
        if (has1 && j > 0) {
            float2 a0 = pr1[0 * Q], a1 = pr1[2 * Q], a2 = pr1[4 * Q], a3 = pr1[6 * Q];
            float2 g0 = pr1[1 * Q], g1 = pr1[3 * Q], g2 = pr1[5 * Q], g3 = pr1[7 * Q];
            float pi = a0.x + a1.x + a2.x + a3.x + b1i;
            float pf = a0.y + a1.y + a2.y + a3.y + b1f;
            float pg = g0.x + g1.x + g2.x + g3.x + b1g;
            float po = g0.y + g1.y + g2.y + g3.y + b1o;
            float gi = sig_fast(pi), gf = sig_fast(pf);
            float gg = tanh_fast(pg), go = sig_fast(po);
            cB = gf * cB + gi * gg;
            hs1[wo] = go * tanh_fast(cB);
        }
        __syncthreads();
    }

    // ========== tail: L1 step T-1 (h1[T-1], h2[T-2] in slot 0) ==========
    {
        const ulonglong2* hp1 = hp1_0;
        const ulonglong2* hp2 = hp2_0;
#pragma unroll
        for (int e = 0; e < EPB; ++e) {
            const int eo = e * 16;
            u64 bA, bB;
            ulonglong2 p = hp1[eo + 0], r = hp1[eo + 1];
            bA = mul2(p.x, w1A[0]); bB = mul2(p.x, w1B[0]);
            bA = fma2(p.y, w1A[1], bA); bB = fma2(p.y, w1B[1], bB);
            bA = fma2(r.x, w1A[2], bA); bB = fma2(r.x, w1B[2], bB);
            bA = fma2(r.y, w1A[3], bA); bB = fma2(r.y, w1B[3], bB);
            p = hp1[eo + 2]; r = hp1[eo + 3];
            bA = fma2(p.x, w1A[4], bA); bB = fma2(p.x, w1B[4], bB);
            bA = fma2(p.y, w1A[5], bA); bB = fma2(p.y, w1B[5], bB);
            bA = fma2(r.x, w1A[6], bA); bB = fma2(r.x, w1B[6], bB);
            bA = fma2(r.y, w1A[7], bA); bB = fma2(r.y, w1B[7], bB);
            p = hp2[eo + 0]; r = hp2[eo + 1];
            bA = fma2(p.x, w1A[8],  bA); bB = fma2(p.x, w1B[8],  bB);
            bA = fma2(p.y, w1A[9],  bA); bB = fma2(p.y, w1B[9],  bB);
            bA = fma2(r.x, w1A[10], bA); bB = fma2(r.x, w1B[10], bB);
            bA = fma2(r.y, w1A[11], bA); bB = fma2(r.y, w1B[11], bB);
            p = hp2[eo + 2]; r = hp2[eo + 3];
            bA = fma2(p.x, w1A[12], bA); bB = fma2(p.x, w1B[12], bB);
            bA = fma2(p.y, w1A[13], bA); bB = fma2(p.y, w1B[13], bB);
            bA = fma2(r.x, w1A[14], bA); bB = fma2(r.x, w1B[14], bB);
            bA = fma2(r.y, w1A[15], bA); bB = fma2(r.y, w1B[15], bB);
            float2 ga = unpack2(bA), gb = unpack2(bB);
            pw1[e * HID] = make_float2(ga.x + ga.y, gb.x + gb.y);
        }
    }
    __syncthreads();
    {
        if (t0L1) {
            float2 a0 = pr0[0 * Q], a1 = pr0[2 * Q], a2 = pr0[4 * Q], a3 = pr0[6 * Q];
            float2 g0 = pr0[1 * Q], g1 = pr0[3 * Q], g2 = pr0[5 * Q], g3 = pr0[7 * Q];
            float pi = a0.x + a1.x + a2.x + a3.x + b1i;
            float pf = a0.y + a1.y + a2.y + a3.y + b1f;
            float pg = g0.x + g1.x + g2.x + g3.x + b1g;
            float po = g0.y + g1.y + g2.y + g3.y + b1o;
            float gi = sig_fast(pi), gf = sig_fast(pf);
            float gg = tanh_fast(pg), go = sig_fast(po);
            cA = gf * cA + gi * gg;
            hs0[Q] = go * tanh_fast(cA);
        }
        if (has1) {
            float2 a0 = pr1[0 * Q], a1 = pr1[2 * Q], a2 = pr1[4 * Q], a3 = pr1[6 * Q];
            float2 g0 = pr1[1 * Q], g1 = pr1[3 * Q], g2 = pr1[5 * Q], g3 = pr1[7 * Q];
            float pi = a0.x + a1.x + a2.x + a3.x + b1i;
            float pf = a0.y + a1.y + a2.y + a3.y + b1f;
            float pg = g0.x + g1.x + g2.x + g3.x + b1g;
            float po = g0.y + g1.y + g2.y + g3.y + b1o;
            float gi = sig_fast(pi), gf = sig_fast(pf);
            float gg = tanh_fast(pg), go = sig_fast(po);
            cB = gf * cB + gi * gg;
            hs1[Q] = go * tanh_fast(cB);
        }
    }
    __syncthreads();

    // ---- final FC: h2[T-1] in slot 1 ----
    if (tid < EPB * 32) {
        const int e = tid >> 5, lane = tid & 31;
        const float* h2l = h2f + Q + e * HID;
        float acc = h2l[lane] * fcW[lane] + h2l[32 + lane] * fcW[32 + lane];
#pragma unroll
        for (int o = 16; o > 0; o >>= 1)
            acc += __shfl_down_sync(0xFFFFFFFFu, acc, o);
        if (lane == 0) {
            int be = b0e + e; if (be > B - 1) be = B - 1;
            out[be] = acc + fcb[0];
        }
    }
}

extern "C" void kernel_launch(void* const* d_in, const int* in_sizes, int n_in,
                              void* d_out, int out_size)
{
    const float* x    = (const float*)d_in[0];
    const float* Wih0 = (const float*)d_in[1];
    const float* Whh0 = (const float*)d_in[2];
    const float* bih0 = (const float*)d_in[3];
    const float* bhh0 = (const float*)d_in[4];
    const float* Wih1 = (const float*)d_in[5];
    const float* Whh1 = (const float*)d_in[6];
    const float* bih1 = (const float*)d_in[7];
    const float* bhh1 = (const float*)d_in[8];
    const float* fcW  = (const float*)d_in[9];
    const float* fcb  = (const float*)d_in[10];
    float* out = (float*)d_out;

    int B = in_sizes[0] / T_STEPS;
    if (B < 1) B = 1;
    int blocks = (B + EPB - 1) / EPB;

    const int smem_bytes = SMEM_FLOATS * 4;
    cudaFuncSetAttribute(lstm_fused, cudaFuncAttributeMaxDynamicSharedMemorySize,
                         smem_bytes);

    lstm_fused<<<blocks, NTHR, smem_bytes>>>(x, Wih0, Whh0, bih0, bhh0,
                                             Wih1, Whh1, bih1, bhh1,
                                             fcW, fcb, out, B);
}

// round 17
// speedup vs baseline: 1.1266x; 1.0227x over previous
#include <cuda_runtime.h>
#include <cstdint>

#define T_STEPS 2048
#define HID 64
#define EPB 7
#define NTHR 512
#define Q (EPB * HID)            // 448: h-slot floats AND psh q-slot stride (float2)

typedef unsigned long long u64;

// ---------- f32x2 packed math ----------
__device__ __forceinline__ u64 fma2(u64 a, u64 b, u64 c) {
    u64 d; asm("fma.rn.f32x2 %0, %1, %2, %3;" : "=l"(d) : "l"(a), "l"(b), "l"(c)); return d;
}
__device__ __forceinline__ u64 mul2(u64 a, u64 b) {
    u64 d; asm("mul.rn.f32x2 %0, %1, %2;" : "=l"(d) : "l"(a), "l"(b)); return d;
}
__device__ __forceinline__ u64 pack2(float lo, float hi) {
    u64 d; asm("mov.b64 %0, {%1, %2};" : "=l"(d) : "f"(lo), "f"(hi)); return d;
}
__device__ __forceinline__ float2 unpack2(u64 v) {
    float a, b; asm("mov.b64 {%0, %1}, %2;" : "=f"(a), "=f"(b) : "l"(v));
    return make_float2(a, b);
}

// ---------- fast activations: MUFU.TANH ----------
__device__ __forceinline__ float tanh_fast(float x) {
    float r; asm("tanh.approx.f32 %0, %1;" : "=f"(r) : "f"(x)); return r;
}
__device__ __forceinline__ float sig_fast(float x) {
    return fmaf(tanh_fast(0.5f * x), 0.5f, 0.5f);
}

extern __shared__ float smem_f[];
// SMEM layout (float offsets)
#define OX   0                          // x: [EPB][T_STEPS]
#define OH1  (EPB * T_STEPS)            // h1: [2][Q]
#define OH2  (OH1 + 2 * Q)              // h2: [2][Q]
#define OP0  (OH2 + 2 * Q)              // psh0: [8][Q] float2
#define OP1  (OP0 + 2 * 8 * Q)          // psh1: [8][Q] float2
#define OB0  (OP1 + 2 * 8 * Q)          // b0s: [64] float4
#define OB1  (OB0 + 4 * HID)            // b1s: [64] float4
#define OXW  (OB1 + 4 * HID)            // xws: [128] float4 (second half zeros)
#define SMEM_FLOATS (OXW + 8 * HID)     // 125952 B

// Phase-1 body: uniform for ALL threads (identical to R13/R16 dataflow).
#define PHASE1_LOOP(HP1, HP2)                                                     \
    _Pragma("unroll")                                                             \
    for (int e = 0; e < EPB; ++e) {                                               \
        const int eo = e * 16;                                                    \
        u64 aA, aB, bA, bB;                                                       \
        ulonglong2 p = (HP1)[eo + 0], r = (HP1)[eo + 1];                          \
        aA = mul2(p.x, w0A[0]);      aB = mul2(p.x, w0B[0]);                      \
        bA = mul2(p.x, w1A[0]);      bB = mul2(p.x, w1B[0]);                      \
        aA = fma2(p.y, w0A[1], aA);  aB = fma2(p.y, w0B[1], aB);                  \
        bA = fma2(p.y, w1A[1], bA);  bB = fma2(p.y, w1B[1], bB);                  \
        aA = fma2(r.x, w0A[2], aA);  aB = fma2(r.x, w0B[2], aB);                  \
        bA = fma2(r.x, w1A[2], bA);  bB = fma2(r.x, w1B[2], bB);                  \
        aA = fma2(r.y, w0A[3], aA);  aB = fma2(r.y, w0B[3], aB);                  \
        bA = fma2(r.y, w1A[3], bA);  bB = fma2(r.y, w1B[3], bB);                  \
        p = (HP1)[eo + 2]; r = (HP1)[eo + 3];                                     \
        aA = fma2(p.x, w0A[4], aA);  aB = fma2(p.x, w0B[4], aB);                  \
        bA = fma2(p.x, w1A[4], bA);  bB = fma2(p.x, w1B[4], bB);                  \
        aA = fma2(p.y, w0A[5], aA);  aB = fma2(p.y, w0B[5], aB);                  \
        bA = fma2(p.y, w1A[5], bA);  bB = fma2(p.y, w1B[5], bB);                  \
        aA = fma2(r.x, w0A[6], aA);  aB = fma2(r.x, w0B[6], aB);                  \
        bA = fma2(r.x, w1A[6], bA);  bB = fma2(r.x, w1B[6], bB);                  \
        aA = fma2(r.y, w0A[7], aA);  aB = fma2(r.y, w0B[7], aB);                  \
        bA = fma2(r.y, w1A[7], bA);  bB = fma2(r.y, w1B[7], bB);                  \
        {                                                                         \
            float2 fa = unpack2(aA), fb = unpack2(aB);                            \
            pw0[e * HID] = make_float2(fa.x + fa.y, fb.x + fb.y);                 \
        }                                                                         \
        p = (HP2)[eo + 0]; r = (HP2)[eo + 1];                                     \
        bA = fma2(p.x, w1A[8],  bA); bB = fma2(p.x, w1B[8],  bB);                 \
        bA = fma2(p.y, w1A[9],  bA); bB = fma2(p.y, w1B[9],  bB);                 \
        bA = fma2(r.x, w1A[10], bA); bB = fma2(r.x, w1B[10], bB);                 \
        bA = fma2(r.y, w1A[11], bA); bB = fma2(r.y, w1B[11], bB);                 \
        p = (HP2)[eo + 2]; r = (HP2)[eo + 3];                                     \
        bA = fma2(p.x, w1A[12], bA); bB = fma2(p.x, w1B[12], bB);                 \
        bA = fma2(p.y, w1A[13], bA); bB = fma2(p.y, w1B[13], bB);                 \
        bA = fma2(r.x, w1A[14], bA); bB = fma2(r.x, w1B[14], bB);                 \
        bA = fma2(r.y, w1A[15], bA); bB = fma2(r.y, w1B[15], bB);                 \
        {                                                                         \
            float2 ga = unpack2(bA), gb = unpack2(bB);                            \
            pw1[e * HID] = make_float2(ga.x + ga.y, gb.x + gb.y);                 \
        }                                                                         \
    }

__global__ void __launch_bounds__(NTHR, 1)
lstm_fused(const float* __restrict__ x,
           const float* __restrict__ Wih0, const float* __restrict__ Whh0,
           const float* __restrict__ bih0, const float* __restrict__ bhh0,
           const float* __restrict__ Wih1, const float* __restrict__ Whh1,
           const float* __restrict__ bih1, const float* __restrict__ bhh1,
           const float* __restrict__ fcW,  const float* __restrict__ fcb,
           float* __restrict__ out, int B)
{
    float*  xs   = smem_f + OX;
    float*  h1f  = smem_f + OH1;
    float*  h2f  = smem_f + OH2;
    float2* psh0 = (float2*)(smem_f + OP0);
    float2* psh1 = (float2*)(smem_f + OP1);
    float4* b0s  = (float4*)(smem_f + OB0);
    float4* b1s  = (float4*)(smem_f + OB1);
    float4* xws  = (float4*)(smem_f + OXW);

    const int tid = threadIdx.x;
    const int u   = tid & 63;
    const int gp  = (tid >> 6) & 1;
    const int s   = tid >> 7;
    const int q   = s * 2 + gp;          // 0..7, warp-uniform
    const int b0e = blockIdx.x * EPB;

    // ---- stage x rows ----
    for (int i = tid; i < EPB * T_STEPS / 4; i += NTHR) {
        int e = i / (T_STEPS / 4), c = i % (T_STEPS / 4);
        int be = b0e + e; if (be > B - 1) be = B - 1;
        ((float4*)xs)[i] = ((const float4*)(x + (size_t)be * T_STEPS))[c];
    }
    for (int i = tid; i < 2 * Q; i += NTHR) { h1f[i] = 0.0f; h2f[i] = 0.0f; }
    // ---- bias / x-weight tables (frees ~12 regs vs per-thread constants) ----
    if (tid < HID) {
        b0s[tid] = make_float4(bih0[tid]       + bhh0[tid],
                               bih0[64 + tid]  + bhh0[64 + tid],
                               bih0[128 + tid] + bhh0[128 + tid],
                               bih0[192 + tid] + bhh0[192 + tid]);
        b1s[tid] = make_float4(bih1[tid]       + bhh1[tid],
                               bih1[64 + tid]  + bhh1[64 + tid],
                               bih1[128 + tid] + bhh1[128 + tid],
                               bih1[192 + tid] + bhh1[192 + tid]);
        xws[tid] = make_float4(Wih0[tid], Wih0[64 + tid],
                               Wih0[128 + tid], Wih0[192 + tid]);
        xws[64 + tid] = make_float4(0.0f, 0.0f, 0.0f, 0.0f);   // zero row for q==7
    }

    // ---- register weights (k-window [16s,16s+16) for BOTH layers) ----
    const int rA = (gp * 2) * 64 + u, rB = (gp * 2 + 1) * 64 + u;
    const int k0 = s * 16;
    u64 w0A[8], w0B[8];
#pragma unroll
    for (int p = 0; p < 8; ++p) {
        w0A[p] = pack2(Whh0[rA * 64 + k0 + 2 * p], Whh0[rA * 64 + k0 + 2 * p + 1]);
        w0B[p] = pack2(Whh0[rB * 64 + k0 + 2 * p], Whh0[rB * 64 + k0 + 2 * p + 1]);
    }
    u64 w1A[16], w1B[16];
#pragma unroll
    for (int p = 0; p < 8; ++p) {
        w1A[p]     = pack2(Wih1[rA * 64 + k0 + 2 * p], Wih1[rA * 64 + k0 + 2 * p + 1]);
        w1B[p]     = pack2(Wih1[rB * 64 + k0 + 2 * p], Wih1[rB * 64 + k0 + 2 * p + 1]);
        w1A[8 + p] = pack2(Whh1[rA * 64 + k0 + 2 * p], Whh1[rA * 64 + k0 + 2 * p + 1]);
        w1B[8 + p] = pack2(Whh1[rB * 64 + k0 + 2 * p], Whh1[rB * 64 + k0 + 2 * p + 1]);
    }

    float2* pw0 = psh0 + q * Q + u;
    float2* pw1 = psh1 + q * Q + u;
    const bool t0L1 = (q == 7);
    const int  e0   = t0L1 ? 0 : q;
    const float2* pr0 = (t0L1 ? psh1 : psh0) + e0 * HID + u;
    float*        hs0 = (t0L1 ? h2f : h1f) + e0 * HID + u;
    const float*  xb0 = xs + e0 * T_STEPS;
    const bool has1 = (q < 6);
    const int  e1   = has1 ? (q + 1) : 0;
    const float2* pr1 = psh1 + e1 * HID + u;
    float*        hs1 = h2f + e1 * HID + u;

    // ---- phase-2 constant POINTERS (3 regs instead of 12 value regs) ----
    const float4* bp0 = (t0L1 ? b1s : b0s) + u;
    const float4* xwp = xws + (t0L1 ? 64 : 0) + u;    // zero row for q==7
    const float4* bp1 = b1s + u;

    // phase-1 read bases for both parities (pointer swap)
    const ulonglong2* hp1_0 = (const ulonglong2*)h1f + s * 4;
    const ulonglong2* hp1_1 = (const ulonglong2*)(h1f + Q) + s * 4;
    const ulonglong2* hp2_0 = (const ulonglong2*)h2f + s * 4;
    const ulonglong2* hp2_1 = (const ulonglong2*)(h2f + Q) + s * 4;

    float cA = 0.0f, cB = 0.0f;
    __syncthreads();

#pragma unroll 1
    for (int j = 0; j < T_STEPS; ++j) {
        const int rb = j & 1;
        const ulonglong2* hp1 = rb ? hp1_1 : hp1_0;
        const ulonglong2* hp2 = rb ? hp2_1 : hp2_0;

        // ========== phase 1 ==========
        PHASE1_LOOP(hp1, hp2)
        __syncthreads();

        // ========== phase 2 ==========
        const int wo = (rb ^ 1) * Q;
        const bool act0 = t0L1 ? (j > 0) : true;
        if (act0) {
            float  xv = xb0[j];
            float4 bb = *bp0;
            float4 xw = *xwp;
            float2 a0 = pr0[0 * Q], a1 = pr0[2 * Q], a2 = pr0[4 * Q], a3 = pr0[6 * Q];
            float2 g0 = pr0[1 * Q], g1 = pr0[3 * Q], g2 = pr0[5 * Q], g3 = pr0[7 * Q];
            float pi = a0.x + a1.x + a2.x + a3.x + fmaf(xv, xw.x, bb.x);
            float pf = a0.y + a1.y + a2.y + a3.y + fmaf(xv, xw.y, bb.y);
            float pg = g0.x + g1.x + g2.x + g3.x + fmaf(xv, xw.z, bb.z);
            float po = g0.y + g1.y + g2.y + g3.y + fmaf(xv, xw.w, bb.w);
            float gi = sig_fast(pi), gf = sig_fast(pf);
            float gg = tanh_fast(pg), go = sig_fast(po);
            cA = gf * cA + gi * gg;
            hs0[wo] = go * tanh_fast(cA);
        }
        if (has1 && j > 0) {
            float4 bb = *bp1;
            float2 a0 = pr1[0 * Q], a1 = pr1[2 * Q], a2 = pr1[4 * Q], a3 = pr1[6 * Q];
            float2 g0 = pr1[1 * Q], g1 = pr1[3 * Q], g2 = pr1[5 * Q], g3 = pr1[7 * Q];
            float pi = a0.x + a1.x + a2.x + a3.x + bb.x;
            float pf = a0.y + a1.y + a2.y + a3.y + bb.y;
            float pg = g0.x + g1.x + g2.x + g3.x + bb.z;
            float po = g0.y + g1.y + g2.y + g3.y + bb.w;
            float gi = sig_fast(pi), gf = sig_fast(pf);
            float gg = tanh_fast(pg), go = sig_fast(po);
            cB = gf * cB + gi * gg;
            hs1[wo] = go * tanh_fast(cB);
        }
        __syncthreads();
    }

    // ========== tail: L1 step T-1 (h1[T-1], h2[T-2] in slot 0) ==========
    {
        const ulonglong2* hp1 = hp1_0;
        const ulonglong2* hp2 = hp2_0;
#pragma unroll
        for (int e = 0; e < EPB; ++e) {
            const int eo = e * 16;
            u64 bA, bB;
            ulonglong2 p = hp1[eo + 0], r = hp1[eo + 1];
            bA = mul2(p.x, w1A[0]); bB = mul2(p.x, w1B[0]);
            bA = fma2(p.y, w1A[1], bA); bB = fma2(p.y, w1B[1], bB);
            bA = fma2(r.x, w1A[2], bA); bB = fma2(r.x, w1B[2], bB);
            bA = fma2(r.y, w1A[3], bA); bB = fma2(r.y, w1B[3], bB);
            p = hp1[eo + 2]; r = hp1[eo + 3];
            bA = fma2(p.x, w1A[4], bA); bB = fma2(p.x, w1B[4], bB);
            bA = fma2(p.y, w1A[5], bA); bB = fma2(p.y, w1B[5], bB);
            bA = fma2(r.x, w1A[6], bA); bB = fma2(r.x, w1B[6], bB);
            bA = fma2(r.y, w1A[7], bA); bB = fma2(r.y, w1B[7], bB);
            p = hp2[eo + 0]; r = hp2[eo + 1];
            bA = fma2(p.x, w1A[8],  bA); bB = fma2(p.x, w1B[8],  bB);
            bA = fma2(p.y, w1A[9],  bA); bB = fma2(p.y, w1B[9],  bB);
            bA = fma2(r.x, w1A[10], bA); bB = fma2(r.x, w1B[10], bB);
            bA = fma2(r.y, w1A[11], bA); bB = fma2(r.y, w1B[11], bB);
            p = hp2[eo + 2]; r = hp2[eo + 3];
            bA = fma2(p.x, w1A[12], bA); bB = fma2(p.x, w1B[12], bB);
            bA = fma2(p.y, w1A[13], bA); bB = fma2(p.y, w1B[13], bB);
            bA = fma2(r.x, w1A[14], bA); bB = fma2(r.x, w1B[14], bB);
            bA = fma2(r.y, w1A[15], bA); bB = fma2(r.y, w1B[15], bB);
            float2 ga = unpack2(bA), gb = unpack2(bB);
            pw1[e * HID] = make_float2(ga.x + ga.y, gb.x + gb.y);
        }
    }
    __syncthreads();
    {
        if (t0L1) {
            float4 bb = *bp0;    // == b1s[u] for q==7
            float2 a0 = pr0[0 * Q], a1 = pr0[2 * Q], a2 = pr0[4 * Q], a3 = pr0[6 * Q];
            float2 g0 = pr0[1 * Q], g1 = pr0[3 * Q], g2 = pr0[5 * Q], g3 = pr0[7 * Q];
            float pi = a0.x + a1.x + a2.x + a3.x + bb.x;
            float pf = a0.y + a1.y + a2.y + a3.y + bb.y;
            float pg = g0.x + g1.x + g2.x + g3.x + bb.z;
            float po = g0.y + g1.y + g2.y + g3.y + bb.w;
            float gi = sig_fast(pi), gf = sig_fast(pf);
            float gg = tanh_fast(pg), go = sig_fast(po);
            cA = gf * cA + gi * gg;
            hs0[Q] = go * tanh_fast(cA);
        }
        if (has1) {
            float4 bb = *bp1;
            float2 a0 = pr1[0 * Q], a1 = pr1[2 * Q], a2 = pr1[4 * Q], a3 = pr1[6 * Q];
            float2 g0 = pr1[1 * Q], g1 = pr1[3 * Q], g2 = pr1[5 * Q], g3 = pr1[7 * Q];
            float pi = a0.x + a1.x + a2.x + a3.x + bb.x;
            float pf = a0.y + a1.y + a2.y + a3.y + bb.y;
            float pg = g0.x + g1.x + g2.x + g3.x + bb.z;
            float po = g0.y + g1.y + g2.y + g3.y + bb.w;
            float gi = sig_fast(pi), gf = sig_fast(pf);
            float gg = tanh_fast(pg), go = sig_fast(po);
            cB = gf * cB + gi * gg;
            hs1[Q] = go * tanh_fast(cB);
        }
    }
    __syncthreads();

    // ---- final FC: h2[T-1] in slot 1 ----
    if (tid < EPB * 32) {
        const int e = tid >> 5, lane = tid & 31;
        const float* h2l = h2f + Q + e * HID;
        float acc = h2l[lane] * fcW[lane] + h2l[32 + lane] * fcW[32 + lane];
#pragma unroll
        for (int o = 16; o > 0; o >>= 1)
            acc += __shfl_down_sync(0xFFFFFFFFu, acc, o);
        if (lane == 0) {
            int be = b0e + e; if (be > B - 1) be = B - 1;
            out[be] = acc + fcb[0];
        }
    }
}

extern "C" void kernel_launch(void* const* d_in, const int* in_sizes, int n_in,
                              void* d_out, int out_size)
{
    const float* x    = (const float*)d_in[0];
    const float* Wih0 = (const float*)d_in[1];
    const float* Whh0 = (const float*)d_in[2];
    const float* bih0 = (const float*)d_in[3];
    const float* bhh0 = (const float*)d_in[4];
    const float* Wih1 = (const float*)d_in[5];
    const float* Whh1 = (const float*)d_in[6];
    const float* bih1 = (const float*)d_in[7];
    const float* bhh1 = (const float*)d_in[8];
    const float* fcW  = (const float*)d_in[9];
    const float* fcb  = (const float*)d_in[10];
    float* out = (float*)d_out;

    int B = in_sizes[0] / T_STEPS;
    if (B < 1) B = 1;
    int blocks = (B + EPB - 1) / EPB;

    const int smem_bytes = SMEM_FLOATS * 4;
    cudaFuncSetAttribute(lstm_fused, cudaFuncAttributeMaxDynamicSharedMemorySize,
                         smem_bytes);

    lstm_fused<<<blocks, NTHR, smem_bytes>>>(x, Wih0, Whh0, bih0, bhh0,
                                             Wih1, Whh1, bih1, bhh1,
                                             fcW, fcb, out, B);
}